// round 1
// baseline (speedup 1.0000x reference)
#include <cuda_runtime.h>

// Problem constants
#define BB   1024   // batch
#define TT   512    // time
#define II   100    // input dim
#define HH   150    // hidden dim
#define HP   160    // padded hidden dim (mult of 32, /4 quads)
#define OO   3      // output classes
#define WPITCH 161  // smem pitch (odd -> conflict-free transpose fill)

// Output tuple layout in d_out (flattened, tuple order): out, hidden, logits
#define OUT_OFF  0
#define HID_OFF  ((size_t)BB * TT * OO)                       // 1,572,864
#define LOG_OFF  (HID_OFF + (size_t)BB * TT * HH)             // 80,216,064

// Scratch: precomputed input projection xw[b*T + t][HP]  (~335 MB)
__device__ float g_xw[(size_t)BB * TT * HP];

// ---------------------------------------------------------------------------
// Kernel 1: xw[bt][j] = sum_i x[bt][i] * W_ih[j][i]   (j padded to 160, pad=0)
// 320 threads: thread = (j = tid%160, half = tid/160), 8 bt-rows per thread.
// ---------------------------------------------------------------------------
__global__ void __launch_bounds__(320) xw_kernel(const float* __restrict__ x,
                                                 const float* __restrict__ W_ih) {
    extern __shared__ float sm[];
    float* WihT = sm;                 // [II][WPITCH]
    float* xs   = sm + II * WPITCH;   // [16][II]
    const int tid = threadIdx.x;

    for (int i = tid; i < II * WPITCH; i += 320) WihT[i] = 0.f;
    __syncthreads();
    for (int idx = tid; idx < HH * II; idx += 320) {
        int h = idx / II, i = idx - h * II;
        WihT[i * WPITCH + h] = W_ih[idx];
    }
    __syncthreads();

    const int j = tid % HP;
    const int half = tid / HP;
    const int nTiles = (BB * TT) / 16;

    for (int tile = blockIdx.x; tile < nTiles; tile += gridDim.x) {
        const int bt0 = tile * 16;
        __syncthreads();  // protect xs against previous iteration's readers
        for (int i2 = tid; i2 < 16 * II; i2 += 320)
            xs[i2] = x[(size_t)bt0 * II + i2];
        __syncthreads();

        float acc[8] = {0.f, 0.f, 0.f, 0.f, 0.f, 0.f, 0.f, 0.f};
        const float* xrow = xs + half * 8 * II;
#pragma unroll
        for (int kq = 0; kq < II / 4; kq++) {
            const float w0 = WihT[(4 * kq + 0) * WPITCH + j];
            const float w1 = WihT[(4 * kq + 1) * WPITCH + j];
            const float w2 = WihT[(4 * kq + 2) * WPITCH + j];
            const float w3 = WihT[(4 * kq + 3) * WPITCH + j];
#pragma unroll
            for (int r = 0; r < 8; r++) {
                float4 xv = *(const float4*)&xrow[r * II + 4 * kq];
                acc[r] = fmaf(xv.x, w0, acc[r]);
                acc[r] = fmaf(xv.y, w1, acc[r]);
                acc[r] = fmaf(xv.z, w2, acc[r]);
                acc[r] = fmaf(xv.w, w3, acc[r]);
            }
        }
#pragma unroll
        for (int r = 0; r < 8; r++)
            g_xw[(size_t)(bt0 + half * 8 + r) * HP + j] = acc[r];
    }
}

// ---------------------------------------------------------------------------
// Kernel 2: sequential RNN. 128 CTAs x 8 batch rows. W_hh^T resident in SMEM.
// One __syncthreads per timestep; ping-pong h buffers.
// ---------------------------------------------------------------------------
__global__ void __launch_bounds__(320) rnn_kernel(const float* __restrict__ h0,
                                                  const float* __restrict__ W_hh,
                                                  float* __restrict__ out) {
    extern __shared__ float sm[];
    float* WhhT = sm;                 // [HP][WPITCH], zero-padded
    float* hs   = sm + HP * WPITCH;   // [2][8][HP]
    const int tid = threadIdx.x;
    const int b0 = blockIdx.x * 8;

    for (int i = tid; i < HP * WPITCH; i += 320) WhhT[i] = 0.f;
    __syncthreads();
    for (int idx = tid; idx < HH * HH; idx += 320) {
        int jj = idx / HH, kk = idx - jj * HH;
        WhhT[kk * WPITCH + jj] = W_hh[idx];   // transposed: WhhT[k][j]
    }
    // stage h0 into buffer 0 (pad k>=150 with 0)
    for (int idx = tid; idx < 8 * HP; idx += 320) {
        int r = idx / HP, k = idx - r * HP;
        hs[r * HP + k] = (k < HH) ? h0[(b0 + r) * HH + k] : 0.f;
    }
    __syncthreads();

    const int j = tid % HP;
    const int half = tid / HP;
    float* hid_out = out + HID_OFF;
    int cur = 0;

    for (int t = 0; t < TT; t++) {
        // issue xw loads early; consumed only in epilogue (latency hidden)
        float xwv[4];
#pragma unroll
        for (int r = 0; r < 4; r++) {
            int b = b0 + half * 4 + r;
            xwv[r] = g_xw[((size_t)b * TT + t) * HP + j];
        }

        float acc[4] = {0.f, 0.f, 0.f, 0.f};
        const float* hcur = hs + cur * (8 * HP) + half * 4 * HP;
#pragma unroll 8
        for (int kq = 0; kq < HP / 4; kq++) {
            const float w0 = WhhT[(4 * kq + 0) * WPITCH + j];
            const float w1 = WhhT[(4 * kq + 1) * WPITCH + j];
            const float w2 = WhhT[(4 * kq + 2) * WPITCH + j];
            const float w3 = WhhT[(4 * kq + 3) * WPITCH + j];
#pragma unroll
            for (int r = 0; r < 4; r++) {
                float4 hv = *(const float4*)&hcur[r * HP + 4 * kq];
                acc[r] = fmaf(hv.x, w0, acc[r]);
                acc[r] = fmaf(hv.y, w1, acc[r]);
                acc[r] = fmaf(hv.z, w2, acc[r]);
                acc[r] = fmaf(hv.w, w3, acc[r]);
            }
        }

        const int nxt = cur ^ 1;
        float* hnxt = hs + nxt * (8 * HP);
#pragma unroll
        for (int r = 0; r < 4; r++) {
            float hval = acc[r] + xwv[r];
            hval = hval > 0.f ? hval : 0.f;   // relu
            hnxt[(half * 4 + r) * HP + j] = hval;
            if (j < HH) {
                int b = b0 + half * 4 + r;
                hid_out[((size_t)b * TT + t) * HH + j] = hval;
            }
        }
        __syncthreads();   // single barrier per step (ping-pong buffers)
        cur = nxt;
    }
}

// ---------------------------------------------------------------------------
// Kernel 3: logits = hidden @ W_fc^T; out = one_hot(argmax(logits + g)).
// One warp per (b,t); 8 warps per CTA. Memory-bound (~315MB hidden re-read).
// ---------------------------------------------------------------------------
__global__ void __launch_bounds__(256) post_kernel(const float* __restrict__ g,
                                                   const float* __restrict__ W_fc,
                                                   float* __restrict__ out) {
    __shared__ float wfc[OO * HP];
    const int tid = threadIdx.x;
    for (int i = tid; i < OO * HP; i += 256) {
        int o = i / HP, k = i - o * HP;
        wfc[i] = (k < HH) ? W_fc[o * HH + k] : 0.f;
    }
    __syncthreads();

    const int warp = tid >> 5, lane = tid & 31;
    const size_t bt = (size_t)blockIdx.x * 8 + warp;
    const float* hid = out + HID_OFF + bt * HH;

    float hv[5];
#pragma unroll
    for (int m = 0; m < 5; m++) {
        int k = lane + 32 * m;
        hv[m] = (k < HH) ? hid[k] : 0.f;
    }
    float p[OO];
#pragma unroll
    for (int o = 0; o < OO; o++) {
        float s = 0.f;
#pragma unroll
        for (int m = 0; m < 5; m++)
            s = fmaf(hv[m], wfc[o * HP + lane + 32 * m], s);
#pragma unroll
        for (int off = 16; off > 0; off >>= 1)
            s += __shfl_xor_sync(0xffffffffu, s, off);
        p[o] = s;
    }
    if (lane == 0) {
        const float z0 = p[0] + g[bt * OO + 0];
        const float z1 = p[1] + g[bt * OO + 1];
        const float z2 = p[2] + g[bt * OO + 2];
        int idx = 0; float best = z0;                 // jnp.argmax: first max
        if (z1 > best) { best = z1; idx = 1; }
        if (z2 > best) { best = z2; idx = 2; }
        float* op = out + bt * OO;
        op[0] = (idx == 0) ? 1.f : 0.f;
        op[1] = (idx == 1) ? 1.f : 0.f;
        op[2] = (idx == 2) ? 1.f : 0.f;
        float* lp = out + LOG_OFF + bt * OO;
        lp[0] = p[0]; lp[1] = p[1]; lp[2] = p[2];
    }
}

// ---------------------------------------------------------------------------
extern "C" void kernel_launch(void* const* d_in, const int* in_sizes, int n_in,
                              void* d_out, int out_size) {
    const float* x    = (const float*)d_in[0];
    const float* h0   = (const float*)d_in[1];
    const float* g    = (const float*)d_in[2];
    const float* W_ih = (const float*)d_in[3];
    const float* W_hh = (const float*)d_in[4];
    const float* W_fc = (const float*)d_in[5];
    float* out = (float*)d_out;

    const int xw_smem  = (II * WPITCH + 16 * II) * (int)sizeof(float);   // ~70.8 KB
    const int rnn_smem = (HP * WPITCH + 2 * 8 * HP) * (int)sizeof(float); // ~113.3 KB
    cudaFuncSetAttribute(xw_kernel,  cudaFuncAttributeMaxDynamicSharedMemorySize, xw_smem);
    cudaFuncSetAttribute(rnn_kernel, cudaFuncAttributeMaxDynamicSharedMemorySize, rnn_smem);

    xw_kernel<<<2048, 320, xw_smem>>>(x, W_ih);
    rnn_kernel<<<BB / 8, 320, rnn_smem>>>(h0, W_hh, out);
    post_kernel<<<(BB * TT) / 8, 256>>>(g, W_fc, out);
}